// round 7
// baseline (speedup 1.0000x reference)
#include <cuda_runtime.h>
#include <cuda_fp16.h>
#include <cuda_bf16.h>
#include <cstdint>

#define DK 128

// -------- device-global scratch --------
__device__ __half g_ABh[100000 * 256];                 // fp16 [node][ A'(=A+b1) | B ]
__device__ __align__(16) unsigned char g_Wsw[65536];   // swizzled bf16 B image [N=256][K=128]

__device__ __forceinline__ uint32_t smem_u32(const void* p) {
    uint32_t a; asm("{ .reg .u64 t; cvta.to.shared.u64 t, %1; cvt.u32.u64 %0, t; }" : "=r"(a) : "l"(p));
    return a;
}
__device__ __forceinline__ uint32_t bf16x2(float lo, float hi) {
    uint32_t r; asm("cvt.rn.bf16x2.f32 %0, %1, %2;" : "=r"(r) : "f"(hi), "f"(lo)); return r;
}
__device__ __forceinline__ uint32_t f16x2(float lo, float hi) {
    __half2 h = __floats2half2_rn(lo, hi); return *(uint32_t*)&h;
}

// Row layout: 256B per row (128 bf16), 16 chunks of 16B, XOR-swizzled by row%8.
__device__ __forceinline__ uint32_t swz(int row, int kchunk) {
    return (uint32_t)(row * 256 + (((kchunk ^ row) & 7) | (kchunk & 8)) * 16);
}

// smem layout (bytes)
#define SM_B1    0                     // 512B: b1 floats
#define SM_A     1024                  // 32 KB: 128 x 128 bf16 (swizzled rows)
#define SM_B     (1024 + 32768)        // 64 KB: 256 x 128 bf16 (swizzled rows)
#define SM_STAGE 1024                  // reuse A+B after mainloop: 128 x 528B
#define SMEM_BYTES (1024 + 32768 + 65536)   // 99328

// ---------------------------------------------------------------------------
// Prep: B[n][k] = W1cat[k][n] as bf16, swizzled. Coalesced LOADS (threads walk
// n), scattered fire-and-forget stores.
// ---------------------------------------------------------------------------
__global__ __launch_bounds__(256)
void w_prep_kernel(const float* __restrict__ W1)
{
    int idx = blockIdx.x * 256 + threadIdx.x;   // 16384 threads
    if (idx >= 16384) return;
    int n  = idx & 255;             // consecutive threads -> consecutive n
    int k2 = (idx >> 8) << 1;       // 0,2,..,126
    float w0, w1;
    if (n < 128) {
        w0 = __ldg(W1 + (size_t)k2 * 128 + n);
        w1 = __ldg(W1 + (size_t)(k2 + 1) * 128 + n);
    } else {
        w0 = __ldg(W1 + (size_t)(128 + k2) * 128 + (n - 128));
        w1 = __ldg(W1 + (size_t)(129 + k2) * 128 + (n - 128));
    }
    uint32_t off = swz(n, k2 >> 3) + (k2 & 7) * 2;
    *(uint32_t*)(g_Wsw + off) = bf16x2(w0, w1);
}

// ---------------------------------------------------------------------------
// Phase 1: HMMA GEMM. 512 threads, M-tile 128, N=256.
// Warp w: rows (w&7)*16, N-half (w>>3). B copy via cp.async.
// ---------------------------------------------------------------------------
__global__ __launch_bounds__(512, 1)
void gemm_mma_kernel(const float* __restrict__ X, const float* __restrict__ b1, int n_nodes)
{
    extern __shared__ unsigned char smem[];
    const uint32_t sb = smem_u32(smem);
    const int tid  = threadIdx.x;
    const int lane = tid & 31;
    const int wid  = tid >> 5;
    const int m0   = blockIdx.x * 128;

    if (tid < 128) *(float*)(smem + SM_B1 + tid * 4) = __ldg(b1 + tid);

    // B image copy: 4096 x 16B via cp.async (overlaps the X convert below)
    #pragma unroll
    for (int t = 0; t < 8; ++t) {
        int i = tid + t * 512;
        uint32_t dst = sb + SM_B + i * 16;
        asm volatile("cp.async.ca.shared.global [%0], [%1], 16;"
                     :: "r"(dst), "l"((const uint4*)g_Wsw + i) : "memory");
    }
    asm volatile("cp.async.commit_group;" ::: "memory");

    // X tile -> bf16, swizzled A smem (zero-fill OOB rows): 4096 float4
    #pragma unroll
    for (int t = 0; t < 8; ++t) {
        int i  = tid + t * 512;
        int m  = i >> 5;
        int k4 = (i & 31) << 2;
        float4 v = make_float4(0.f, 0.f, 0.f, 0.f);
        if (m0 + m < n_nodes) v = *(const float4*)(X + (size_t)(m0 + m) * DK + k4);
        uint32_t off = swz(m, k4 >> 3) + (k4 & 7) * 2;
        *(uint2*)(smem + SM_A + off) = make_uint2(bf16x2(v.x, v.y), bf16x2(v.z, v.w));
    }
    asm volatile("cp.async.wait_all;" ::: "memory");
    __syncthreads();

    const int half = wid >> 3;
    const int m0w  = (wid & 7) * 16;

    const int a_row     = m0w + ((lane >> 3) & 1) * 8 + (lane & 7);
    const int a_koff    = lane >> 4;
    const int b_rowbase = half * 128 + ((lane >> 4) & 1) * 8 + (lane & 7);
    const int b_koff    = (lane >> 3) & 1;

    float acc[16][4];
    #pragma unroll
    for (int nb = 0; nb < 16; ++nb)
        #pragma unroll
        for (int j = 0; j < 4; ++j) acc[nb][j] = 0.f;

    #pragma unroll 1
    for (int ks = 0; ks < 8; ++ks) {
        uint32_t a0, a1, a2, a3;
        uint32_t aaddr = sb + SM_A + swz(a_row, ks * 2 + a_koff);
        asm volatile("ldmatrix.sync.aligned.m8n8.x4.shared.b16 {%0,%1,%2,%3}, [%4];"
                     : "=r"(a0), "=r"(a1), "=r"(a2), "=r"(a3) : "r"(aaddr));

        #pragma unroll
        for (int nb16 = 0; nb16 < 8; ++nb16) {
            uint32_t b0, b1r, b2r, b3r;
            uint32_t baddr = sb + SM_B + swz(b_rowbase + nb16 * 16, ks * 2 + b_koff);
            asm volatile("ldmatrix.sync.aligned.m8n8.x4.shared.b16 {%0,%1,%2,%3}, [%4];"
                         : "=r"(b0), "=r"(b1r), "=r"(b2r), "=r"(b3r) : "r"(baddr));
            asm volatile(
                "mma.sync.aligned.m16n8k16.row.col.f32.bf16.bf16.f32 "
                "{%0,%1,%2,%3}, {%4,%5,%6,%7}, {%8,%9}, {%0,%1,%2,%3};"
                : "+f"(acc[2*nb16][0]), "+f"(acc[2*nb16][1]), "+f"(acc[2*nb16][2]), "+f"(acc[2*nb16][3])
                : "r"(a0), "r"(a1), "r"(a2), "r"(a3), "r"(b0), "r"(b1r));
            asm volatile(
                "mma.sync.aligned.m16n8k16.row.col.f32.bf16.bf16.f32 "
                "{%0,%1,%2,%3}, {%4,%5,%6,%7}, {%8,%9}, {%0,%1,%2,%3};"
                : "+f"(acc[2*nb16+1][0]), "+f"(acc[2*nb16+1][1]), "+f"(acc[2*nb16+1][2]), "+f"(acc[2*nb16+1][3])
                : "r"(a0), "r"(a1), "r"(a2), "r"(a3), "r"(b2r), "r"(b3r));
        }
    }
    __syncthreads();   // A/B smem dead; reuse as staging

    {   // Epilogue: +b1 on half 0, fp16 pack, conflict-free staging.
        const int mA = m0w + (lane >> 2);
        const int cq = (lane & 3) * 2;
        #pragma unroll
        for (int nb = 0; nb < 16; ++nb) {
            int n = nb * 8 + cq;
            float add0 = 0.f, add1 = 0.f;
            if (half == 0) {
                float2 bb = *(const float2*)(smem + SM_B1 + n * 4);
                add0 = bb.x; add1 = bb.y;
            }
            uint32_t lo = f16x2(acc[nb][0] + add0, acc[nb][1] + add1);
            uint32_t hi = f16x2(acc[nb][2] + add0, acc[nb][3] + add1);
            uint32_t col = (half * 128 + n) * 2;
            *(uint32_t*)(smem + SM_STAGE + mA * 528 + col)       = lo;
            *(uint32_t*)(smem + SM_STAGE + (mA + 8) * 528 + col) = hi;
        }
    }
    __syncthreads();

    // Coalesced STG: 128 rows x 512B contiguous in g_ABh (4096 uint4).
    uint4* out4 = (uint4*)(g_ABh) + (size_t)m0 * 32;
    #pragma unroll
    for (int t = 0; t < 8; ++t) {
        int i   = tid + t * 512;
        int row = i >> 5;
        int c4  = i & 31;
        if (m0 + row < n_nodes)
            out4[(size_t)row * 32 + c4] = *(const uint4*)(smem + SM_STAGE + row * 528 + c4 * 16);
    }
}

// ---------------------------------------------------------------------------
// Phase 2: half-warp per edge; deeper unroll for more gathers in flight.
// ---------------------------------------------------------------------------
__global__ __launch_bounds__(256)
void edge_kernel(const int* __restrict__ eidx,
                 const float* __restrict__ W2,
                 const float* __restrict__ b2,
                 float* __restrict__ out, int n_edges, int n_nodes)
{
    __shared__ float sres[8][32];

    const int lane = threadIdx.x & 31;
    const int wid  = threadIdx.x >> 5;
    const int base = (blockIdx.x * 8 + wid) * 32;
    if (base >= n_edges) return;

    const int hl = lane & 15;   // lane within half-warp: components hl*8 .. hl*8+7
    const int hw = lane >> 4;   // which edge of the pair

    float wd[8];
    #pragma unroll
    for (int t = 0; t < 4; ++t) {
        float4 w = __ldg(((const float4*)W2) + hl * 4 + t);
        wd[2*t]   = w.x - w.y;
        wd[2*t+1] = w.z - w.w;
    }
    const float b2d = __ldg(b2 + 0) - __ldg(b2 + 1);

    int el = base + lane;
    bool valid = el < n_edges;
    int si = valid ? __ldg(eidx + el) : 0;
    int di = valid ? __ldg(eidx + n_edges + el) : 0;
    si = min(max(si, 0), n_nodes - 1);
    di = min(max(di, 0), n_nodes - 1);

    const __half2 z2 = __float2half2_rn(0.f);

    #pragma unroll 4
    for (int i = 0; i < 16; ++i) {
        int s = __shfl_sync(0xffffffffu, si, 2 * i + hw);
        int d = __shfl_sync(0xffffffffu, di, 2 * i + hw);

        uint4 av = __ldg(((const uint4*)(g_ABh + (size_t)s * 256)) + hl);
        uint4 bv = __ldg(((const uint4*)(g_ABh + (size_t)d * 256 + 128)) + hl);

        __half2 h0 = __hmax2(__hadd2(*(__half2*)&av.x, *(__half2*)&bv.x), z2);
        __half2 h1 = __hmax2(__hadd2(*(__half2*)&av.y, *(__half2*)&bv.y), z2);
        __half2 h2 = __hmax2(__hadd2(*(__half2*)&av.z, *(__half2*)&bv.z), z2);
        __half2 h3 = __hmax2(__hadd2(*(__half2*)&av.w, *(__half2*)&bv.w), z2);

        float2 f0 = __half22float2(h0);
        float2 f1 = __half22float2(h1);
        float2 f2 = __half22float2(h2);
        float2 f3 = __half22float2(h3);

        float dlt = f0.x * wd[0];
        dlt = fmaf(f0.y, wd[1], dlt);
        dlt = fmaf(f1.x, wd[2], dlt);
        dlt = fmaf(f1.y, wd[3], dlt);
        dlt = fmaf(f2.x, wd[4], dlt);
        dlt = fmaf(f2.y, wd[5], dlt);
        dlt = fmaf(f3.x, wd[6], dlt);
        dlt = fmaf(f3.y, wd[7], dlt);

        #pragma unroll
        for (int o = 8; o; o >>= 1)
            dlt += __shfl_xor_sync(0xffffffffu, dlt, o);

        if (hl == 0) sres[wid][2 * i + hw] = dlt;
    }
    __syncwarp();

    if (valid) {
        float d0 = sres[wid][lane] + b2d;     // = s0 - s1
        float e  = __expf(-d0);
        float c  = 1.f / (1.f + e);
        out[el]           = c;
        out[n_edges + el] = e * c;
    }
}

extern "C" void kernel_launch(void* const* d_in, const int* in_sizes, int n_in,
                              void* d_out, int out_size)
{
    const float* X    = (const float*)d_in[0];
    const int*   eidx = (const int*)d_in[1];     // int32 on device
    const float* W1   = (const float*)d_in[2];
    const float* b1   = (const float*)d_in[3];
    const float* W2   = (const float*)d_in[4];
    const float* b2   = (const float*)d_in[5];
    float* out = (float*)d_out;

    const int n_nodes = in_sizes[0] / DK;   // 100000
    const int n_edges = in_sizes[1] / 2;    // 640000

    w_prep_kernel<<<64, 256>>>(W1);

    cudaFuncSetAttribute(gemm_mma_kernel, cudaFuncAttributeMaxDynamicSharedMemorySize, SMEM_BYTES);
    int gemm_blocks = (n_nodes + 127) / 128;   // 782
    gemm_mma_kernel<<<gemm_blocks, 512, SMEM_BYTES>>>(X, b1, n_nodes);

    int edge_blocks = (n_edges + 255) / 256;
    edge_kernel<<<edge_blocks, 256>>>(eidx, W2, b2, out, n_edges, n_nodes);
}